// round 11
// baseline (speedup 1.0000x reference)
#include <cuda_runtime.h>
#include <cuda_fp16.h>
#include <cstdint>

#define NN 100000
#define NE 1600000
#define HID 128
#define NG 64
#define NC 10

// ---------------------------------------------------------------------------
// Persistent scratch (static __device__ arrays — no runtime allocation).
// ---------------------------------------------------------------------------
__device__ __half g_h1h[NN * HID];     // fp16 activations (ping)
__device__ __half g_h2h[NN * HID];     // fp16 activations (pong)
__device__ float g_inv[NN];
__device__ float g_pool[NG * HID];
__device__ float g_gcnt[NG];
// CSR
__device__ int g_deg[NN];
__device__ int g_rowptr[NN + 1];
__device__ int g_cursor[NN];
__device__ int g_csrc[NE];
__device__ int g_bsum[512];
__device__ int g_boff[512];
// Pre-split fp16 B chunk images: 2 layers x 8 chunks x [64 k][136 n(pad)]
// chunks 0-3 = Wh (K 0..255), chunks 4-7 = Wl residual.
__device__ uint32_t g_Bp[2 * 8 * 4352];

// ---------------------------------------------------------------------------
// Helpers
// ---------------------------------------------------------------------------
__device__ __forceinline__ uint32_t smem_u32(const void* p) {
    uint32_t a;
    asm("{ .reg .u64 t; cvta.to.shared.u64 t, %1; cvt.u32.u64 %0, t; }"
        : "=r"(a) : "l"(p));
    return a;
}

__device__ __forceinline__ uint32_t pack_h2(__half lo, __half hi) {
    return ((uint32_t)__half_as_ushort(hi) << 16) | __half_as_ushort(lo);
}

__device__ __forceinline__ void ldmatrix_x4(uint32_t r[4], uint32_t addr) {
    asm volatile("ldmatrix.sync.aligned.m8n8.x4.shared.b16 {%0,%1,%2,%3}, [%4];"
                 : "=r"(r[0]), "=r"(r[1]), "=r"(r[2]), "=r"(r[3]) : "r"(addr));
}

__device__ __forceinline__ void ldmatrix_x2t(uint32_t& b0, uint32_t& b1, uint32_t addr) {
    asm volatile("ldmatrix.sync.aligned.m8n8.x2.trans.shared.b16 {%0,%1}, [%2];"
                 : "=r"(b0), "=r"(b1) : "r"(addr));
}

__device__ __forceinline__ void mma_f16(float d[4], const uint32_t a[4],
                                        uint32_t b0, uint32_t b1) {
    asm volatile(
        "mma.sync.aligned.m16n8k16.row.col.f32.f16.f16.f32 "
        "{%0,%1,%2,%3}, {%4,%5,%6,%7}, {%8,%9}, {%0,%1,%2,%3};"
        : "+f"(d[0]), "+f"(d[1]), "+f"(d[2]), "+f"(d[3])
        : "r"(a[0]), "r"(a[1]), "r"(a[2]), "r"(a[3]), "r"(b0), "r"(b1));
}

#define ACC8(u) do {                                                  \
    float2 _p;                                                        \
    _p = __half22float2(*(__half2*)&(u).x); a0 += _p.x; a1 += _p.y;   \
    _p = __half22float2(*(__half2*)&(u).y); a2 += _p.x; a3 += _p.y;   \
    _p = __half22float2(*(__half2*)&(u).z); a4 += _p.x; a5 += _p.y;   \
    _p = __half22float2(*(__half2*)&(u).w); a6 += _p.x; a7 += _p.y;   \
} while (0)

// ---------------------------------------------------------------------------
// CSR build: degree histogram -> scan -> fill
// ---------------------------------------------------------------------------
__global__ void k_deg(const int* __restrict__ ei, int E) {
    int e = blockIdx.x * blockDim.x + threadIdx.x;
    if (e < E) atomicAdd(&g_deg[ei[E + e]], 1);
}

__global__ void k_scan1(int N) {
    __shared__ int s[256];
    int idx = blockIdx.x * 256 + threadIdx.x;
    int v = (idx < N) ? g_deg[idx] : 0;
    s[threadIdx.x] = v;
    __syncthreads();
    for (int off = 128; off > 0; off >>= 1) {
        if (threadIdx.x < off) s[threadIdx.x] += s[threadIdx.x + off];
        __syncthreads();
    }
    if (threadIdx.x == 0) g_bsum[blockIdx.x] = s[0];
}

__global__ void k_scan2(int nb, int E) {
    int lane = threadIdx.x;  // one warp
    int run = 0;
    for (int base = 0; base < nb; base += 32) {
        int i = base + lane;
        int orig = (i < nb) ? g_bsum[i] : 0;
        int v = orig;
#pragma unroll
        for (int off = 1; off < 32; off <<= 1) {
            int t = __shfl_up_sync(0xffffffff, v, off);
            if (lane >= off) v += t;
        }
        if (i < nb) g_boff[i] = run + v - orig;
        run += __shfl_sync(0xffffffff, v, 31);
    }
    if (lane == 0) g_rowptr[NN] = E;
}

__global__ void k_scan3(int N) {
    __shared__ int s[256];
    int t = threadIdx.x;
    int idx = blockIdx.x * 256 + t;
    int v = (idx < N) ? g_deg[idx] : 0;
    s[t] = v;
    __syncthreads();
#pragma unroll
    for (int off = 1; off < 256; off <<= 1) {
        int add = (t >= off) ? s[t - off] : 0;
        __syncthreads();
        s[t] += add;
        __syncthreads();
    }
    if (idx < N) {
        int ex = s[t] - v + g_boff[blockIdx.x];
        g_rowptr[idx] = ex;
        g_cursor[idx] = ex;
    }
}

__global__ void k_fill(const int* __restrict__ ei, int E) {
    int e = blockIdx.x * blockDim.x + threadIdx.x;
    if (e < E) {
        int s = ei[e];
        int d = ei[E + e];
        int pos = atomicAdd(&g_cursor[d], 1);
        g_csrc[pos] = s;
    }
}

__global__ void k_gcnt(const int* __restrict__ batch, int N) {
    int t = blockIdx.x * blockDim.x + threadIdx.x;
    int n0 = t * 32;
    if (n0 >= N) return;
    int ne = min(n0 + 32, N);
    int cur = batch[n0];
    float c = 0.0f;
    for (int n = n0; n < ne; n++) {
        int b = batch[n];
        if (b != cur) { atomicAdd(&g_gcnt[cur], c); c = 0.0f; cur = b; }
        c += 1.0f;
    }
    atomicAdd(&g_gcnt[cur], c);
}

// ---------------------------------------------------------------------------
// Fused CSR scalar aggregation + layer 1: warp per node. Writes g_inv too.
// ---------------------------------------------------------------------------
__global__ void k_layer1f(const float* __restrict__ x,
                          const float* __restrict__ W1l,
                          const float* __restrict__ W1r,
                          const float* __restrict__ b1, int N) {
    int wid = threadIdx.x >> 5;
    int lane = threadIdx.x & 31;
    int node = blockIdx.x * 8 + wid;
    if (node >= N) return;
    int beg = g_rowptr[node], end = g_rowptr[node + 1];
    float s = 0.0f;
    for (int i = beg + lane; i < end; i += 32) s += __ldg(&x[g_csrc[i]]);
#pragma unroll
    for (int off = 16; off > 0; off >>= 1)
        s += __shfl_xor_sync(0xffffffff, s, off);
    float inv = 1.0f / fmaxf((float)(end - beg), 1.0f);
    if (lane == 0) g_inv[node] = inv;
    float mean = s * inv;
    float xv = __ldg(&x[node]);
    int j = lane * 4;
    float4 wl = *(const float4*)(W1l + j);
    float4 wr = *(const float4*)(W1r + j);
    float4 bb = *(const float4*)(b1 + j);
    float v0 = fmaxf(fmaf(mean, wl.x, fmaf(xv, wr.x, bb.x)), 0.0f);
    float v1 = fmaxf(fmaf(mean, wl.y, fmaf(xv, wr.y, bb.y)), 0.0f);
    float v2 = fmaxf(fmaf(mean, wl.z, fmaf(xv, wr.z, bb.z)), 0.0f);
    float v3 = fmaxf(fmaf(mean, wl.w, fmaf(xv, wr.w, bb.w)), 0.0f);
    uint2 o;
    *(__half2*)&o.x = __floats2half2_rn(v0, v1);
    *(__half2*)&o.y = __floats2half2_rn(v2, v3);
    *(uint2*)(g_h1h + (size_t)node * HID + j) = o;
}

// ---------------------------------------------------------------------------
// Weight prep (both layers in one launch): fp16 2-term split.
// chunks 0-3 = Wh (K 0..255), 4-7 = Wl = fp16(W - Wh).
// ---------------------------------------------------------------------------
__global__ void k_prepB(const float* __restrict__ W2l, const float* __restrict__ W2r,
                        const float* __restrict__ W3l, const float* __restrict__ W3r) {
    int t = blockIdx.x * blockDim.x + threadIdx.x;
    if (t >= 2 * 8 * 64 * 64) return;
    int layer = t >> 15;
    int tt = t & 32767;
    const float* Wl = layer ? W3l : W2l;
    const float* Wr = layer ? W3r : W2r;
    int ci = tt >> 12;
    int rem = tt & 4095;
    int k = rem >> 6;
    int np = rem & 63;
    int n = np * 2;
    int kk = (ci & 3) * 64 + k;
    float w0 = (kk < 128) ? Wl[kk * HID + n] : Wr[(kk - 128) * HID + n];
    float w1 = (kk < 128) ? Wl[kk * HID + n + 1] : Wr[(kk - 128) * HID + n + 1];
    __half p0, p1;
    if (ci < 4) {
        p0 = __float2half_rn(w0);
        p1 = __float2half_rn(w1);
    } else {
        __half h0 = __float2half_rn(w0), h1 = __float2half_rn(w1);
        p0 = __float2half_rn(w0 - __half2float(h0));
        p1 = __float2half_rn(w1 - __half2float(h1));
    }
    g_Bp[layer * 34816 + ci * 4352 + k * 68 + np] = pack_h2(p0, p1);
}

// ---------------------------------------------------------------------------
// FUSED gather + SAGE GEMM (fp16 mma, 2-term weight split, K_eff = 512):
//   A-tile row = [mean(node) | hin(node)]; mean gathered IN-KERNEL from CSR.
//   pool_mode=0: hout = relu(A@W + b) -> fp16
//   pool_mode=1: relu values accumulated into g_pool (no hout store)
// 64x128 tile / block, 256 threads, occ 3.
// smem: A[64][264 fp16] (33792B) | B dbuf (2x17408B) = 68608B total
// ---------------------------------------------------------------------------
#define AP 528          // A row stride bytes (264 fp16, odd 16B-stride)
#define BP 272          // B row stride bytes (136 fp16)
#define SM_B  33792
#define BCH   17408
#define SMEM_GEMM (33792 + 2 * 17408)

__device__ __forceinline__ void prefB(uint32_t smdst, const uint32_t* src, int tid) {
#pragma unroll
    for (int m = 0; m < 5; m++) {
        int i = tid + m * 256;
        if (i < 1088)
            asm volatile("cp.async.cg.shared.global [%0], [%1], 16;"
                         :: "r"(smdst + i * 16), "l"((const uint4*)src + i) : "memory");
    }
    asm volatile("cp.async.commit_group;" ::: "memory");
}

__global__ __launch_bounds__(256, 3)
void k_gemm(const __half* __restrict__ hin, __half* __restrict__ hout,
            const float* __restrict__ bias, const int* __restrict__ batch,
            int layer, int pool_mode, int N) {
    extern __shared__ char sm[];
    uint32_t smb = smem_u32(sm);
    int tid = threadIdx.x;
    int lane = tid & 31;
    int wid = tid >> 5;
    int n0 = blockIdx.x * 64;
    const uint32_t* Bpl = g_Bp + layer * 34816;

    // --- Stage hin half-rows via cp.async: 64 rows x 16 chunks = 1024 ---
#pragma unroll
    for (int m = 0; m < 4; m++) {
        int idx = tid + m * 256;
        int r = idx >> 4;
        int c16 = idx & 15;
        int node = n0 + r;
        uint32_t dst = smb + (uint32_t)(r * AP + 256 + c16 * 16);
        if (node < N) {
            const char* src = (const char*)(hin + (size_t)node * HID) + c16 * 16;
            asm volatile("cp.async.cg.shared.global [%0], [%1], 16;"
                         :: "r"(dst), "l"(src) : "memory");
        } else {
            asm volatile("st.shared.v4.b32 [%0], {%1,%1,%1,%1};"
                         :: "r"(dst), "r"(0u) : "memory");
        }
    }
    asm volatile("cp.async.commit_group;" ::: "memory");

    // B chunk 0,1 prefetch (commit groups: hin, c0, c1)
    prefB(smb + SM_B, Bpl, tid);
    prefB(smb + SM_B + BCH, Bpl + 4352, tid);

    // --- In-kernel CSR gather of neighbor means into A cols 0..127 ---
    // Half-warp per node, 4 passes; edge loop unrolled x4 for MLP.
    {
        int hw = lane >> 4;
        int sl = lane & 15;     // 16B chunk within the 256B mean half-row
#pragma unroll
        for (int pass = 0; pass < 4; pass++) {
            int nl = wid * 8 + pass * 2 + hw;
            int node = n0 + nl;
            float a0 = 0.f, a1 = 0.f, a2 = 0.f, a3 = 0.f;
            float a4 = 0.f, a5 = 0.f, a6 = 0.f, a7 = 0.f;
            float inv = 1.0f;
            if (node < N) {
                int beg = g_rowptr[node], end = g_rowptr[node + 1];
                inv = g_inv[node];
                int i = beg;
                for (; i + 3 < end; i += 4) {
                    int s0 = g_csrc[i], s1 = g_csrc[i + 1];
                    int s2 = g_csrc[i + 2], s3 = g_csrc[i + 3];
                    uint4 u0 = __ldg((const uint4*)(hin + (size_t)s0 * HID) + sl);
                    uint4 u1 = __ldg((const uint4*)(hin + (size_t)s1 * HID) + sl);
                    uint4 u2 = __ldg((const uint4*)(hin + (size_t)s2 * HID) + sl);
                    uint4 u3 = __ldg((const uint4*)(hin + (size_t)s3 * HID) + sl);
                    ACC8(u0); ACC8(u1); ACC8(u2); ACC8(u3);
                }
                for (; i < end; i++) {
                    int s0 = g_csrc[i];
                    uint4 u0 = __ldg((const uint4*)(hin + (size_t)s0 * HID) + sl);
                    ACC8(u0);
                }
            }
            uint4 o;
            *(__half2*)&o.x = __floats2half2_rn(a0 * inv, a1 * inv);
            *(__half2*)&o.y = __floats2half2_rn(a2 * inv, a3 * inv);
            *(__half2*)&o.z = __floats2half2_rn(a4 * inv, a5 * inv);
            *(__half2*)&o.w = __floats2half2_rn(a6 * inv, a7 * inv);
            uint32_t dst = smb + (uint32_t)(nl * AP + sl * 16);
            asm volatile("st.shared.v4.b32 [%0], {%1,%2,%3,%4};"
                         :: "r"(dst), "r"(o.x), "r"(o.y), "r"(o.z), "r"(o.w)
                         : "memory");
        }
    }

    float acc[2][4][4];
#pragma unroll
    for (int s = 0; s < 2; s++)
#pragma unroll
        for (int nt = 0; nt < 4; nt++)
#pragma unroll
            for (int q = 0; q < 4; q++) acc[s][nt][q] = 0.0f;

    int wr = wid & 1;          // 2 row groups of 32
    int wc = wid >> 1;         // 4 col groups of 32
    int a_r = lane & 15;
    int a_c8 = (lane >> 4) << 3;
    int b_r = lane & 15;

    for (int ci = 0; ci < 8; ci++) {
        if (ci >= 1 && ci < 7)
            prefB(smb + SM_B + ((ci + 1) & 1) * BCH, Bpl + (ci + 1) * 4352, tid);
        if (ci < 7) asm volatile("cp.async.wait_group 1;" ::: "memory");
        else        asm volatile("cp.async.wait_group 0;" ::: "memory");
        __syncthreads();

        int kc = ci & 3;                 // Wh: 0-3, Wl: 4-7 reuse same A cols
        int acol0 = kc * 64;
        uint32_t bbuf = smb + SM_B + (uint32_t)(ci & 1) * BCH;

#pragma unroll
        for (int ks = 0; ks < 4; ks++) {
            int k0 = acol0 + ks * 16;
            uint32_t a0[4], a1[4];
            uint32_t addr0 = smb + (uint32_t)((wr * 32 + a_r) * AP + (k0 + a_c8) * 2);
            ldmatrix_x4(a0, addr0);
            ldmatrix_x4(a1, addr0 + 16 * AP);
            uint32_t bbase = bbuf + (uint32_t)((ks * 16 + b_r) * BP + wc * 64);
#pragma unroll
            for (int nt = 0; nt < 4; nt++) {
                uint32_t b0, b1;
                ldmatrix_x2t(b0, b1, bbase + nt * 16);
                mma_f16(acc[0][nt], a0, b0, b1);
                mma_f16(acc[1][nt], a1, b0, b1);
            }
        }
        __syncthreads();
    }

    int qr = lane >> 2;
    int qc = (lane & 3) * 2;

    if (!pool_mode) {
        // --- Epilogue: bias + relu -> fp16 store ---
#pragma unroll
        for (int s = 0; s < 2; s++) {
            int mb = n0 + wr * 32 + s * 16;
#pragma unroll
            for (int nt = 0; nt < 4; nt++) {
                int col = wc * 32 + nt * 8 + qc;
                float2 bv = *(const float2*)(bias + col);
                int mlo = mb + qr;
                int mhi = mlo + 8;
                if (mlo < N) {
                    float o0 = fmaxf(acc[s][nt][0] + bv.x, 0.f);
                    float o1 = fmaxf(acc[s][nt][1] + bv.y, 0.f);
                    *(__half2*)(hout + (size_t)mlo * HID + col) = __floats2half2_rn(o0, o1);
                }
                if (mhi < N) {
                    float o0 = fmaxf(acc[s][nt][2] + bv.x, 0.f);
                    float o1 = fmaxf(acc[s][nt][3] + bv.y, 0.f);
                    *(__half2*)(hout + (size_t)mhi * HID + col) = __floats2half2_rn(o0, o1);
                }
            }
        }
    } else {
        // --- Epilogue: bias + relu -> per-block smem pool, then global ---
        // B smem buffer is dead now; reuse as pool accumulator.
        float* ps = (float*)(sm + SM_B);   // up to 64 graphs x 128 cols
        int nlast = min(n0 + 63, N - 1);
        int gmin = __ldg(&batch[n0]);
        int gmax = __ldg(&batch[nlast]);
        int ngr = gmax - gmin + 1;
        for (int i = tid; i < ngr * HID; i += 256) ps[i] = 0.0f;
        __syncthreads();
#pragma unroll
        for (int s = 0; s < 2; s++) {
            int mb = n0 + wr * 32 + s * 16;
#pragma unroll
            for (int nt = 0; nt < 4; nt++) {
                int col = wc * 32 + nt * 8 + qc;
                float2 bv = *(const float2*)(bias + col);
                int mlo = mb + qr;
                int mhi = mlo + 8;
                if (mlo < N) {
                    int g = __ldg(&batch[mlo]) - gmin;
                    atomicAdd(&ps[g * HID + col],     fmaxf(acc[s][nt][0] + bv.x, 0.f));
                    atomicAdd(&ps[g * HID + col + 1], fmaxf(acc[s][nt][1] + bv.y, 0.f));
                }
                if (mhi < N) {
                    int g = __ldg(&batch[mhi]) - gmin;
                    atomicAdd(&ps[g * HID + col],     fmaxf(acc[s][nt][2] + bv.x, 0.f));
                    atomicAdd(&ps[g * HID + col + 1], fmaxf(acc[s][nt][3] + bv.y, 0.f));
                }
            }
        }
        __syncthreads();
        for (int i = tid; i < ngr * HID; i += 256)
            atomicAdd(&g_pool[(gmin + i / HID) * HID + (i & 127)], ps[i]);
    }
}

// ---------------------------------------------------------------------------
// Head: logits = (pool/gcnt) @ Wfc + bfc ; log_softmax
// ---------------------------------------------------------------------------
__global__ void k_head(const float* __restrict__ Wfc,
                       const float* __restrict__ bfc,
                       float* __restrict__ out) {
    __shared__ float lg[NG][NC];
    int t = threadIdx.x;
    if (t < NG * NC) {
        int g = t / NC;
        int c = t % NC;
        float ginv = 1.0f / fmaxf(g_gcnt[g], 1.0f);
        float s = __ldg(&bfc[c]);
        for (int k = 0; k < HID; k++)
            s = fmaf(g_pool[g * HID + k] * ginv, __ldg(&Wfc[k * NC + c]), s);
        lg[g][c] = s;
    }
    __syncthreads();
    if (t < NG) {
        float m = -1e30f;
        for (int c = 0; c < NC; c++) m = fmaxf(m, lg[t][c]);
        float se = 0.0f;
        for (int c = 0; c < NC; c++) se += expf(lg[t][c] - m);
        float lse = m + logf(se);
        for (int c = 0; c < NC; c++) out[t * NC + c] = lg[t][c] - lse;
    }
}

// ---------------------------------------------------------------------------
extern "C" void kernel_launch(void* const* d_in, const int* in_sizes, int n_in,
                              void* d_out, int out_size) {
    const float* x   = (const float*)d_in[0];
    const int* ei    = (const int*)d_in[1];
    const int* batch = (const int*)d_in[2];
    const float* W1l = (const float*)d_in[3];
    const float* W1r = (const float*)d_in[4];
    const float* b1  = (const float*)d_in[5];
    const float* W2l = (const float*)d_in[6];
    const float* W2r = (const float*)d_in[7];
    const float* b2  = (const float*)d_in[8];
    const float* W3l = (const float*)d_in[9];
    const float* W3r = (const float*)d_in[10];
    const float* b3  = (const float*)d_in[11];
    const float* Wfc = (const float*)d_in[12];
    const float* bfc = (const float*)d_in[13];
    float* out = (float*)d_out;

    int N = in_sizes[0];
    int E = in_sizes[1] / 2;
    int nb = (N + 255) / 256;

    void *p_deg, *p_gcnt, *p_pool, *p_h1, *p_h2;
    cudaGetSymbolAddress(&p_deg, g_deg);
    cudaGetSymbolAddress(&p_gcnt, g_gcnt);
    cudaGetSymbolAddress(&p_pool, g_pool);
    cudaGetSymbolAddress(&p_h1, g_h1h);
    cudaGetSymbolAddress(&p_h2, g_h2h);

    cudaFuncSetAttribute(k_gemm, cudaFuncAttributeMaxDynamicSharedMemorySize, SMEM_GEMM);

    cudaMemsetAsync(p_deg, 0, (size_t)N * 4);
    cudaMemsetAsync(p_gcnt, 0, NG * 4);
    cudaMemsetAsync(p_pool, 0, NG * HID * 4);

    // CSR build
    k_deg<<<(E + 255) / 256, 256>>>(ei, E);
    k_scan1<<<nb, 256>>>(N);
    k_scan2<<<1, 32>>>(nb, E);
    k_scan3<<<nb, 256>>>(N);
    k_fill<<<(E + 255) / 256, 256>>>(ei, E);

    // Prep + layer 1 (fused CSR scalar agg + transform)
    k_gcnt<<<((N + 31) / 32 + 255) / 256, 256>>>(batch, N);
    k_prepB<<<256, 256>>>(W2l, W2r, W3l, W3r);
    k_layer1f<<<(N + 7) / 8, 256>>>(x, W1l, W1r, b1, N);

    int gemm_blocks = (N + 63) / 64;

    // Layer 2 (fused gather+gemm)
    k_gemm<<<gemm_blocks, 256, SMEM_GEMM>>>((const __half*)p_h1, (__half*)p_h2,
                                            b2, batch, 0, 0, N);

    // Layer 3 (fused gather+gemm+pool; no activation store)
    k_gemm<<<gemm_blocks, 256, SMEM_GEMM>>>((const __half*)p_h2, (__half*)p_h1,
                                            b3, batch, 1, 1, N);

    // Head
    k_head<<<1, 640>>>(Wfc, bfc, out);
}

// round 13
// speedup vs baseline: 1.0310x; 1.0310x over previous
#include <cuda_runtime.h>
#include <cuda_fp16.h>
#include <cstdint>

#define NN 100000
#define NE 1600000
#define HID 128
#define NG 64
#define NC 10

// ---------------------------------------------------------------------------
// Persistent scratch (static __device__ arrays — no runtime allocation).
// ---------------------------------------------------------------------------
__device__ __half g_h1h[NN * HID];     // fp16 activations (ping)
__device__ __half g_h2h[NN * HID];     // fp16 activations (pong)
__device__ float g_inv[NN];
__device__ float g_pool[NG * HID];
__device__ float g_gcnt[NG];
// CSR
__device__ int g_deg[NN];
__device__ int g_rowptr[NN + 1];
__device__ int g_cursor[NN];
__device__ int g_csrc[NE];
__device__ int g_bsum[512];
__device__ int g_boff[512];
// Pre-split fp16 B chunk images: 2 layers x 8 chunks x [64 k][136 n(pad)]
// chunks 0-3 = Wh (K 0..255), chunks 4-7 = Wl residual.
__device__ uint32_t g_Bp[2 * 8 * 4352];

// ---------------------------------------------------------------------------
// Helpers
// ---------------------------------------------------------------------------
__device__ __forceinline__ uint32_t smem_u32(const void* p) {
    uint32_t a;
    asm("{ .reg .u64 t; cvta.to.shared.u64 t, %1; cvt.u32.u64 %0, t; }"
        : "=r"(a) : "l"(p));
    return a;
}

__device__ __forceinline__ uint32_t pack_h2(__half lo, __half hi) {
    return ((uint32_t)__half_as_ushort(hi) << 16) | __half_as_ushort(lo);
}

__device__ __forceinline__ void ldmatrix_x4(uint32_t r[4], uint32_t addr) {
    asm volatile("ldmatrix.sync.aligned.m8n8.x4.shared.b16 {%0,%1,%2,%3}, [%4];"
                 : "=r"(r[0]), "=r"(r[1]), "=r"(r[2]), "=r"(r[3]) : "r"(addr));
}

__device__ __forceinline__ void ldmatrix_x2t(uint32_t& b0, uint32_t& b1, uint32_t addr) {
    asm volatile("ldmatrix.sync.aligned.m8n8.x2.trans.shared.b16 {%0,%1}, [%2];"
                 : "=r"(b0), "=r"(b1) : "r"(addr));
}

__device__ __forceinline__ void mma_f16(float d[4], const uint32_t a[4],
                                        uint32_t b0, uint32_t b1) {
    asm volatile(
        "mma.sync.aligned.m16n8k16.row.col.f32.f16.f16.f32 "
        "{%0,%1,%2,%3}, {%4,%5,%6,%7}, {%8,%9}, {%0,%1,%2,%3};"
        : "+f"(d[0]), "+f"(d[1]), "+f"(d[2]), "+f"(d[3])
        : "r"(a[0]), "r"(a[1]), "r"(a[2]), "r"(a[3]), "r"(b0), "r"(b1));
}

// ---------------------------------------------------------------------------
// CSR build: degree histogram -> scan -> fill
// ---------------------------------------------------------------------------
__global__ void k_deg(const int* __restrict__ ei, int E) {
    int e = blockIdx.x * blockDim.x + threadIdx.x;
    if (e < E) atomicAdd(&g_deg[ei[E + e]], 1);
}

__global__ void k_scan1(int N) {
    __shared__ int s[256];
    int idx = blockIdx.x * 256 + threadIdx.x;
    int v = (idx < N) ? g_deg[idx] : 0;
    s[threadIdx.x] = v;
    __syncthreads();
    for (int off = 128; off > 0; off >>= 1) {
        if (threadIdx.x < off) s[threadIdx.x] += s[threadIdx.x + off];
        __syncthreads();
    }
    if (threadIdx.x == 0) g_bsum[blockIdx.x] = s[0];
}

__global__ void k_scan2(int nb, int E) {
    int lane = threadIdx.x;  // one warp
    int run = 0;
    for (int base = 0; base < nb; base += 32) {
        int i = base + lane;
        int orig = (i < nb) ? g_bsum[i] : 0;
        int v = orig;
#pragma unroll
        for (int off = 1; off < 32; off <<= 1) {
            int t = __shfl_up_sync(0xffffffff, v, off);
            if (lane >= off) v += t;
        }
        if (i < nb) g_boff[i] = run + v - orig;
        run += __shfl_sync(0xffffffff, v, 31);
    }
    if (lane == 0) g_rowptr[NN] = E;
}

__global__ void k_scan3(int N) {
    __shared__ int s[256];
    int t = threadIdx.x;
    int idx = blockIdx.x * 256 + t;
    int v = (idx < N) ? g_deg[idx] : 0;
    s[t] = v;
    __syncthreads();
#pragma unroll
    for (int off = 1; off < 256; off <<= 1) {
        int add = (t >= off) ? s[t - off] : 0;
        __syncthreads();
        s[t] += add;
        __syncthreads();
    }
    if (idx < N) {
        int ex = s[t] - v + g_boff[blockIdx.x];
        g_rowptr[idx] = ex;
        g_cursor[idx] = ex;
    }
}

__global__ void k_fill(const int* __restrict__ ei, int E) {
    int e = blockIdx.x * blockDim.x + threadIdx.x;
    if (e < E) {
        int s = ei[e];
        int d = ei[E + e];
        int pos = atomicAdd(&g_cursor[d], 1);
        g_csrc[pos] = s;
    }
}

__global__ void k_gcnt(const int* __restrict__ batch, int N) {
    int t = blockIdx.x * blockDim.x + threadIdx.x;
    int n0 = t * 32;
    if (n0 >= N) return;
    int ne = min(n0 + 32, N);
    int cur = batch[n0];
    float c = 0.0f;
    for (int n = n0; n < ne; n++) {
        int b = batch[n];
        if (b != cur) { atomicAdd(&g_gcnt[cur], c); c = 0.0f; cur = b; }
        c += 1.0f;
    }
    atomicAdd(&g_gcnt[cur], c);
}

// ---------------------------------------------------------------------------
// Fused CSR scalar aggregation + layer 1: warp per node. Writes g_inv too.
// ---------------------------------------------------------------------------
__global__ void k_layer1f(const float* __restrict__ x,
                          const float* __restrict__ W1l,
                          const float* __restrict__ W1r,
                          const float* __restrict__ b1, int N) {
    int wid = threadIdx.x >> 5;
    int lane = threadIdx.x & 31;
    int node = blockIdx.x * 8 + wid;
    if (node >= N) return;
    int beg = g_rowptr[node], end = g_rowptr[node + 1];
    float s = 0.0f;
    for (int i = beg + lane; i < end; i += 32) s += __ldg(&x[g_csrc[i]]);
#pragma unroll
    for (int off = 16; off > 0; off >>= 1)
        s += __shfl_xor_sync(0xffffffff, s, off);
    float inv = 1.0f / fmaxf((float)(end - beg), 1.0f);
    if (lane == 0) g_inv[node] = inv;
    float mean = s * inv;
    float xv = __ldg(&x[node]);
    int j = lane * 4;
    float4 wl = *(const float4*)(W1l + j);
    float4 wr = *(const float4*)(W1r + j);
    float4 bb = *(const float4*)(b1 + j);
    float v0 = fmaxf(fmaf(mean, wl.x, fmaf(xv, wr.x, bb.x)), 0.0f);
    float v1 = fmaxf(fmaf(mean, wl.y, fmaf(xv, wr.y, bb.y)), 0.0f);
    float v2 = fmaxf(fmaf(mean, wl.z, fmaf(xv, wr.z, bb.z)), 0.0f);
    float v3 = fmaxf(fmaf(mean, wl.w, fmaf(xv, wr.w, bb.w)), 0.0f);
    uint2 o;
    *(__half2*)&o.x = __floats2half2_rn(v0, v1);
    *(__half2*)&o.y = __floats2half2_rn(v2, v3);
    *(uint2*)(g_h1h + (size_t)node * HID + j) = o;
}

// ---------------------------------------------------------------------------
// Weight prep (both layers in one launch): fp16 2-term split.
// chunks 0-3 = Wh (K 0..255), 4-7 = Wl = fp16(W - Wh).
// ---------------------------------------------------------------------------
__global__ void k_prepB(const float* __restrict__ W2l, const float* __restrict__ W2r,
                        const float* __restrict__ W3l, const float* __restrict__ W3r) {
    int t = blockIdx.x * blockDim.x + threadIdx.x;
    if (t >= 2 * 8 * 64 * 64) return;
    int layer = t >> 15;
    int tt = t & 32767;
    const float* Wl = layer ? W3l : W2l;
    const float* Wr = layer ? W3r : W2r;
    int ci = tt >> 12;
    int rem = tt & 4095;
    int k = rem >> 6;
    int np = rem & 63;
    int n = np * 2;
    int kk = (ci & 3) * 64 + k;
    float w0 = (kk < 128) ? Wl[kk * HID + n] : Wr[(kk - 128) * HID + n];
    float w1 = (kk < 128) ? Wl[kk * HID + n + 1] : Wr[(kk - 128) * HID + n + 1];
    __half p0, p1;
    if (ci < 4) {
        p0 = __float2half_rn(w0);
        p1 = __float2half_rn(w1);
    } else {
        __half h0 = __float2half_rn(w0), h1 = __float2half_rn(w1);
        p0 = __float2half_rn(w0 - __half2float(h0));
        p1 = __float2half_rn(w1 - __half2float(h1));
    }
    g_Bp[layer * 34816 + ci * 4352 + k * 68 + np] = pack_h2(p0, p1);
}

// ---------------------------------------------------------------------------
// FUSED gather + SAGE GEMM (fp16 mma, 2-term weight split, K_eff = 512):
//   A-tile row = [mean(node) | hin(node)]; mean gathered IN-KERNEL from CSR
//   (2-edge unroll — R10 form; 4-wide spilled under the occ-3 reg cap).
//   pool_mode=0: hout = relu(A@W + b) -> fp16
//   pool_mode=1: relu values accumulated into g_pool (no hout store)
// 64x128 tile / block, 256 threads, occ 3.
// smem: A[64][264 fp16] (33792B) | B dbuf (2x17408B) = 68608B total
// ---------------------------------------------------------------------------
#define AP 528          // A row stride bytes (264 fp16, odd 16B-stride)
#define BP 272          // B row stride bytes (136 fp16)
#define SM_B  33792
#define BCH   17408
#define SMEM_GEMM (33792 + 2 * 17408)

__device__ __forceinline__ void prefB(uint32_t smdst, const uint32_t* src, int tid) {
#pragma unroll
    for (int m = 0; m < 5; m++) {
        int i = tid + m * 256;
        if (i < 1088)
            asm volatile("cp.async.cg.shared.global [%0], [%1], 16;"
                         :: "r"(smdst + i * 16), "l"((const uint4*)src + i) : "memory");
    }
    asm volatile("cp.async.commit_group;" ::: "memory");
}

__global__ __launch_bounds__(256, 3)
void k_gemm(const __half* __restrict__ hin, __half* __restrict__ hout,
            const float* __restrict__ bias, const int* __restrict__ batch,
            int layer, int pool_mode, int N) {
    extern __shared__ char sm[];
    uint32_t smb = smem_u32(sm);
    int tid = threadIdx.x;
    int lane = tid & 31;
    int wid = tid >> 5;
    int n0 = blockIdx.x * 64;
    const uint32_t* Bpl = g_Bp + layer * 34816;

    // --- Stage hin half-rows via cp.async: 64 rows x 16 chunks = 1024 ---
#pragma unroll
    for (int m = 0; m < 4; m++) {
        int idx = tid + m * 256;
        int r = idx >> 4;
        int c16 = idx & 15;
        int node = n0 + r;
        uint32_t dst = smb + (uint32_t)(r * AP + 256 + c16 * 16);
        if (node < N) {
            const char* src = (const char*)(hin + (size_t)node * HID) + c16 * 16;
            asm volatile("cp.async.cg.shared.global [%0], [%1], 16;"
                         :: "r"(dst), "l"(src) : "memory");
        } else {
            asm volatile("st.shared.v4.b32 [%0], {%1,%1,%1,%1};"
                         :: "r"(dst), "r"(0u) : "memory");
        }
    }
    asm volatile("cp.async.commit_group;" ::: "memory");

    // B chunk 0,1 prefetch (commit groups: hin, c0, c1)
    prefB(smb + SM_B, Bpl, tid);
    prefB(smb + SM_B + BCH, Bpl + 4352, tid);

    // --- In-kernel CSR gather of neighbor means into A cols 0..127 ---
    // Half-warp per node, 4 passes; 2-edge unroll (R10 form).
    {
        int hw = lane >> 4;
        int sl = lane & 15;     // 16B chunk within the 256B mean half-row
#pragma unroll
        for (int pass = 0; pass < 4; pass++) {
            int nl = wid * 8 + pass * 2 + hw;
            int node = n0 + nl;
            float a0 = 0.f, a1 = 0.f, a2 = 0.f, a3 = 0.f;
            float a4 = 0.f, a5 = 0.f, a6 = 0.f, a7 = 0.f;
            float inv = 1.0f;
            if (node < N) {
                int beg = g_rowptr[node], end = g_rowptr[node + 1];
                inv = g_inv[node];
                int i = beg;
                for (; i + 1 < end; i += 2) {
                    int s0 = g_csrc[i], s1 = g_csrc[i + 1];
                    uint4 u0 = __ldg((const uint4*)(hin + (size_t)s0 * HID) + sl);
                    uint4 u1 = __ldg((const uint4*)(hin + (size_t)s1 * HID) + sl);
                    float2 p;
                    p = __half22float2(*(__half2*)&u0.x); a0 += p.x; a1 += p.y;
                    p = __half22float2(*(__half2*)&u0.y); a2 += p.x; a3 += p.y;
                    p = __half22float2(*(__half2*)&u0.z); a4 += p.x; a5 += p.y;
                    p = __half22float2(*(__half2*)&u0.w); a6 += p.x; a7 += p.y;
                    p = __half22float2(*(__half2*)&u1.x); a0 += p.x; a1 += p.y;
                    p = __half22float2(*(__half2*)&u1.y); a2 += p.x; a3 += p.y;
                    p = __half22float2(*(__half2*)&u1.z); a4 += p.x; a5 += p.y;
                    p = __half22float2(*(__half2*)&u1.w); a6 += p.x; a7 += p.y;
                }
                if (i < end) {
                    int s0 = g_csrc[i];
                    uint4 u0 = __ldg((const uint4*)(hin + (size_t)s0 * HID) + sl);
                    float2 p;
                    p = __half22float2(*(__half2*)&u0.x); a0 += p.x; a1 += p.y;
                    p = __half22float2(*(__half2*)&u0.y); a2 += p.x; a3 += p.y;
                    p = __half22float2(*(__half2*)&u0.z); a4 += p.x; a5 += p.y;
                    p = __half22float2(*(__half2*)&u0.w); a6 += p.x; a7 += p.y;
                }
            }
            uint4 o;
            *(__half2*)&o.x = __floats2half2_rn(a0 * inv, a1 * inv);
            *(__half2*)&o.y = __floats2half2_rn(a2 * inv, a3 * inv);
            *(__half2*)&o.z = __floats2half2_rn(a4 * inv, a5 * inv);
            *(__half2*)&o.w = __floats2half2_rn(a6 * inv, a7 * inv);
            uint32_t dst = smb + (uint32_t)(nl * AP + sl * 16);
            asm volatile("st.shared.v4.b32 [%0], {%1,%2,%3,%4};"
                         :: "r"(dst), "r"(o.x), "r"(o.y), "r"(o.z), "r"(o.w)
                         : "memory");
        }
    }

    float acc[2][4][4];
#pragma unroll
    for (int s = 0; s < 2; s++)
#pragma unroll
        for (int nt = 0; nt < 4; nt++)
#pragma unroll
            for (int q = 0; q < 4; q++) acc[s][nt][q] = 0.0f;

    int wr = wid & 1;          // 2 row groups of 32
    int wc = wid >> 1;         // 4 col groups of 32
    int a_r = lane & 15;
    int a_c8 = (lane >> 4) << 3;
    int b_r = lane & 15;

    for (int ci = 0; ci < 8; ci++) {
        if (ci >= 1 && ci < 7)
            prefB(smb + SM_B + ((ci + 1) & 1) * BCH, Bpl + (ci + 1) * 4352, tid);
        if (ci < 7) asm volatile("cp.async.wait_group 1;" ::: "memory");
        else        asm volatile("cp.async.wait_group 0;" ::: "memory");
        __syncthreads();

        int kc = ci & 3;                 // Wh: 0-3, Wl: 4-7 reuse same A cols
        int acol0 = kc * 64;
        uint32_t bbuf = smb + SM_B + (uint32_t)(ci & 1) * BCH;

#pragma unroll
        for (int ks = 0; ks < 4; ks++) {
            int k0 = acol0 + ks * 16;
            uint32_t a0[4], a1[4];
            uint32_t addr0 = smb + (uint32_t)((wr * 32 + a_r) * AP + (k0 + a_c8) * 2);
            ldmatrix_x4(a0, addr0);
            ldmatrix_x4(a1, addr0 + 16 * AP);
            uint32_t bbase = bbuf + (uint32_t)((ks * 16 + b_r) * BP + wc * 64);
#pragma unroll
            for (int nt = 0; nt < 4; nt++) {
                uint32_t b0, b1;
                ldmatrix_x2t(b0, b1, bbase + nt * 16);
                mma_f16(acc[0][nt], a0, b0, b1);
                mma_f16(acc[1][nt], a1, b0, b1);
            }
        }
        __syncthreads();
    }

    int qr = lane >> 2;
    int qc = (lane & 3) * 2;

    if (!pool_mode) {
        // --- Epilogue: bias + relu -> fp16 store ---
#pragma unroll
        for (int s = 0; s < 2; s++) {
            int mb = n0 + wr * 32 + s * 16;
#pragma unroll
            for (int nt = 0; nt < 4; nt++) {
                int col = wc * 32 + nt * 8 + qc;
                float2 bv = *(const float2*)(bias + col);
                int mlo = mb + qr;
                int mhi = mlo + 8;
                if (mlo < N) {
                    float o0 = fmaxf(acc[s][nt][0] + bv.x, 0.f);
                    float o1 = fmaxf(acc[s][nt][1] + bv.y, 0.f);
                    *(__half2*)(hout + (size_t)mlo * HID + col) = __floats2half2_rn(o0, o1);
                }
                if (mhi < N) {
                    float o0 = fmaxf(acc[s][nt][2] + bv.x, 0.f);
                    float o1 = fmaxf(acc[s][nt][3] + bv.y, 0.f);
                    *(__half2*)(hout + (size_t)mhi * HID + col) = __floats2half2_rn(o0, o1);
                }
            }
        }
    } else {
        // --- Epilogue: bias + relu -> per-block smem pool, then global ---
        // B smem buffer is dead now; reuse as pool accumulator.
        float* ps = (float*)(sm + SM_B);   // up to 64 graphs x 128 cols
        int nlast = min(n0 + 63, N - 1);
        int gmin = __ldg(&batch[n0]);
        int gmax = __ldg(&batch[nlast]);
        int ngr = gmax - gmin + 1;
        for (int i = tid; i < ngr * HID; i += 256) ps[i] = 0.0f;
        __syncthreads();
#pragma unroll
        for (int s = 0; s < 2; s++) {
            int mb = n0 + wr * 32 + s * 16;
#pragma unroll
            for (int nt = 0; nt < 4; nt++) {
                int col = wc * 32 + nt * 8 + qc;
                float2 bv = *(const float2*)(bias + col);
                int mlo = mb + qr;
                int mhi = mlo + 8;
                if (mlo < N) {
                    int g = __ldg(&batch[mlo]) - gmin;
                    atomicAdd(&ps[g * HID + col],     fmaxf(acc[s][nt][0] + bv.x, 0.f));
                    atomicAdd(&ps[g * HID + col + 1], fmaxf(acc[s][nt][1] + bv.y, 0.f));
                }
                if (mhi < N) {
                    int g = __ldg(&batch[mhi]) - gmin;
                    atomicAdd(&ps[g * HID + col],     fmaxf(acc[s][nt][2] + bv.x, 0.f));
                    atomicAdd(&ps[g * HID + col + 1], fmaxf(acc[s][nt][3] + bv.y, 0.f));
                }
            }
        }
        __syncthreads();
        for (int i = tid; i < ngr * HID; i += 256)
            atomicAdd(&g_pool[(gmin + i / HID) * HID + (i & 127)], ps[i]);
    }
}

// ---------------------------------------------------------------------------
// Head: logits = (pool/gcnt) @ Wfc + bfc ; log_softmax
// ---------------------------------------------------------------------------
__global__ void k_head(const float* __restrict__ Wfc,
                       const float* __restrict__ bfc,
                       float* __restrict__ out) {
    __shared__ float lg[NG][NC];
    int t = threadIdx.x;
    if (t < NG * NC) {
        int g = t / NC;
        int c = t % NC;
        float ginv = 1.0f / fmaxf(g_gcnt[g], 1.0f);
        float s = __ldg(&bfc[c]);
        for (int k = 0; k < HID; k++)
            s = fmaf(g_pool[g * HID + k] * ginv, __ldg(&Wfc[k * NC + c]), s);
        lg[g][c] = s;
    }
    __syncthreads();
    if (t < NG) {
        float m = -1e30f;
        for (int c = 0; c < NC; c++) m = fmaxf(m, lg[t][c]);
        float se = 0.0f;
        for (int c = 0; c < NC; c++) se += expf(lg[t][c] - m);
        float lse = m + logf(se);
        for (int c = 0; c < NC; c++) out[t * NC + c] = lg[t][c] - lse;
    }
}

// ---------------------------------------------------------------------------
extern "C" void kernel_launch(void* const* d_in, const int* in_sizes, int n_in,
                              void* d_out, int out_size) {
    const float* x   = (const float*)d_in[0];
    const int* ei    = (const int*)d_in[1];
    const int* batch = (const int*)d_in[2];
    const float* W1l = (const float*)d_in[3];
    const float* W1r = (const float*)d_in[4];
    const float* b1  = (const float*)d_in[5];
    const float* W2l = (const float*)d_in[6];
    const float* W2r = (const float*)d_in[7];
    const float* b2  = (const float*)d_in[8];
    const float* W3l = (const float*)d_in[9];
    const float* W3r = (const float*)d_in[10];
    const float* b3  = (const float*)d_in[11];
    const float* Wfc = (const float*)d_in[12];
    const float* bfc = (const float*)d_in[13];
    float* out = (float*)d_out;

    int N = in_sizes[0];
    int E = in_sizes[1] / 2;
    int nb = (N + 255) / 256;

    void *p_deg, *p_gcnt, *p_pool, *p_h1, *p_h2;
    cudaGetSymbolAddress(&p_deg, g_deg);
    cudaGetSymbolAddress(&p_gcnt, g_gcnt);
    cudaGetSymbolAddress(&p_pool, g_pool);
    cudaGetSymbolAddress(&p_h1, g_h1h);
    cudaGetSymbolAddress(&p_h2, g_h2h);

    cudaFuncSetAttribute(k_gemm, cudaFuncAttributeMaxDynamicSharedMemorySize, SMEM_GEMM);

    cudaMemsetAsync(p_deg, 0, (size_t)N * 4);
    cudaMemsetAsync(p_gcnt, 0, NG * 4);
    cudaMemsetAsync(p_pool, 0, NG * HID * 4);

    // CSR build
    k_deg<<<(E + 255) / 256, 256>>>(ei, E);
    k_scan1<<<nb, 256>>>(N);
    k_scan2<<<1, 32>>>(nb, E);
    k_scan3<<<nb, 256>>>(N);
    k_fill<<<(E + 255) / 256, 256>>>(ei, E);

    // Prep + layer 1 (fused CSR scalar agg + transform)
    k_gcnt<<<((N + 31) / 32 + 255) / 256, 256>>>(batch, N);
    k_prepB<<<256, 256>>>(W2l, W2r, W3l, W3r);
    k_layer1f<<<(N + 7) / 8, 256>>>(x, W1l, W1r, b1, N);

    int gemm_blocks = (N + 63) / 64;

    // Layer 2 (fused gather+gemm)
    k_gemm<<<gemm_blocks, 256, SMEM_GEMM>>>((const __half*)p_h1, (__half*)p_h2,
                                            b2, batch, 0, 0, N);

    // Layer 3 (fused gather+gemm+pool; no activation store)
    k_gemm<<<gemm_blocks, 256, SMEM_GEMM>>>((const __half*)p_h2, (__half*)p_h1,
                                            b3, batch, 1, 1, N);

    // Head
    k_head<<<1, 640>>>(Wfc, bfc, out);
}

// round 15
// speedup vs baseline: 1.0381x; 1.0068x over previous
#include <cuda_runtime.h>
#include <cuda_fp16.h>
#include <cstdint>

#define NN 100000
#define NE 1600000
#define HID 128
#define NG 64
#define NC 10

// ---------------------------------------------------------------------------
// Persistent scratch (static __device__ arrays — no runtime allocation).
// ---------------------------------------------------------------------------
__device__ __half g_h1h[NN * HID];     // fp16 activations (ping)
__device__ __half g_h2h[NN * HID];     // fp16 activations (pong)
__device__ float g_inv[NN];
__device__ float g_pool[NG * HID];
__device__ float g_gcnt[NG];
// CSR
__device__ int g_deg[NN];
__device__ int g_rowptr[NN + 1];
__device__ int g_cursor[NN];
__device__ int g_csrc[NE];
__device__ int g_bsum[512];
__device__ int g_boff[512];
// Pre-split fp16 B chunk images: 2 layers x 8 chunks x [64 k][136 n(pad)]
// chunks 0-3 = Wh (K 0..255), chunks 4-7 = Wl residual.
__device__ uint32_t g_Bp[2 * 8 * 4352];

// ---------------------------------------------------------------------------
// Helpers
// ---------------------------------------------------------------------------
__device__ __forceinline__ uint32_t smem_u32(const void* p) {
    uint32_t a;
    asm("{ .reg .u64 t; cvta.to.shared.u64 t, %1; cvt.u32.u64 %0, t; }"
        : "=r"(a) : "l"(p));
    return a;
}

__device__ __forceinline__ uint32_t pack_h2(__half lo, __half hi) {
    return ((uint32_t)__half_as_ushort(hi) << 16) | __half_as_ushort(lo);
}

__device__ __forceinline__ void ldmatrix_x4(uint32_t r[4], uint32_t addr) {
    asm volatile("ldmatrix.sync.aligned.m8n8.x4.shared.b16 {%0,%1,%2,%3}, [%4];"
                 : "=r"(r[0]), "=r"(r[1]), "=r"(r[2]), "=r"(r[3]) : "r"(addr));
}

__device__ __forceinline__ void ldmatrix_x2t(uint32_t& b0, uint32_t& b1, uint32_t addr) {
    asm volatile("ldmatrix.sync.aligned.m8n8.x2.trans.shared.b16 {%0,%1}, [%2];"
                 : "=r"(b0), "=r"(b1) : "r"(addr));
}

__device__ __forceinline__ void mma_f16(float d[4], const uint32_t a[4],
                                        uint32_t b0, uint32_t b1) {
    asm volatile(
        "mma.sync.aligned.m16n8k16.row.col.f32.f16.f16.f32 "
        "{%0,%1,%2,%3}, {%4,%5,%6,%7}, {%8,%9}, {%0,%1,%2,%3};"
        : "+f"(d[0]), "+f"(d[1]), "+f"(d[2]), "+f"(d[3])
        : "r"(a[0]), "r"(a[1]), "r"(a[2]), "r"(a[3]), "r"(b0), "r"(b1));
}

// ---------------------------------------------------------------------------
// CSR build: degree histogram -> scan -> fill
// ---------------------------------------------------------------------------
__global__ void k_deg(const int* __restrict__ ei, int E) {
    int e = blockIdx.x * blockDim.x + threadIdx.x;
    if (e < E) atomicAdd(&g_deg[ei[E + e]], 1);
}

__global__ void k_scan1(int N) {
    __shared__ int s[256];
    int idx = blockIdx.x * 256 + threadIdx.x;
    int v = (idx < N) ? g_deg[idx] : 0;
    s[threadIdx.x] = v;
    __syncthreads();
    for (int off = 128; off > 0; off >>= 1) {
        if (threadIdx.x < off) s[threadIdx.x] += s[threadIdx.x + off];
        __syncthreads();
    }
    if (threadIdx.x == 0) g_bsum[blockIdx.x] = s[0];
}

__global__ void k_scan2(int nb, int E) {
    int lane = threadIdx.x;  // one warp
    int run = 0;
    for (int base = 0; base < nb; base += 32) {
        int i = base + lane;
        int orig = (i < nb) ? g_bsum[i] : 0;
        int v = orig;
#pragma unroll
        for (int off = 1; off < 32; off <<= 1) {
            int t = __shfl_up_sync(0xffffffff, v, off);
            if (lane >= off) v += t;
        }
        if (i < nb) g_boff[i] = run + v - orig;
        run += __shfl_sync(0xffffffff, v, 31);
    }
    if (lane == 0) g_rowptr[NN] = E;
}

__global__ void k_scan3(int N) {
    __shared__ int s[256];
    int t = threadIdx.x;
    int idx = blockIdx.x * 256 + t;
    int v = (idx < N) ? g_deg[idx] : 0;
    s[t] = v;
    __syncthreads();
#pragma unroll
    for (int off = 1; off < 256; off <<= 1) {
        int add = (t >= off) ? s[t - off] : 0;
        __syncthreads();
        s[t] += add;
        __syncthreads();
    }
    if (idx < N) {
        int ex = s[t] - v + g_boff[blockIdx.x];
        g_rowptr[idx] = ex;
        g_cursor[idx] = ex;
    }
}

__global__ void k_fill(const int* __restrict__ ei, int E) {
    int e = blockIdx.x * blockDim.x + threadIdx.x;
    if (e < E) {
        int s = ei[e];
        int d = ei[E + e];
        int pos = atomicAdd(&g_cursor[d], 1);
        g_csrc[pos] = s;
    }
}

__global__ void k_gcnt(const int* __restrict__ batch, int N) {
    int t = blockIdx.x * blockDim.x + threadIdx.x;
    int n0 = t * 32;
    if (n0 >= N) return;
    int ne = min(n0 + 32, N);
    int cur = batch[n0];
    float c = 0.0f;
    for (int n = n0; n < ne; n++) {
        int b = batch[n];
        if (b != cur) { atomicAdd(&g_gcnt[cur], c); c = 0.0f; cur = b; }
        c += 1.0f;
    }
    atomicAdd(&g_gcnt[cur], c);
}

// ---------------------------------------------------------------------------
// Fused CSR scalar aggregation + layer 1: warp per node. Writes g_inv too.
// ---------------------------------------------------------------------------
__global__ void k_layer1f(const float* __restrict__ x,
                          const float* __restrict__ W1l,
                          const float* __restrict__ W1r,
                          const float* __restrict__ b1, int N) {
    int wid = threadIdx.x >> 5;
    int lane = threadIdx.x & 31;
    int node = blockIdx.x * 8 + wid;
    if (node >= N) return;
    int beg = g_rowptr[node], end = g_rowptr[node + 1];
    float s = 0.0f;
    for (int i = beg + lane; i < end; i += 32) s += __ldg(&x[g_csrc[i]]);
#pragma unroll
    for (int off = 16; off > 0; off >>= 1)
        s += __shfl_xor_sync(0xffffffff, s, off);
    float inv = 1.0f / fmaxf((float)(end - beg), 1.0f);
    if (lane == 0) g_inv[node] = inv;
    float mean = s * inv;
    float xv = __ldg(&x[node]);
    int j = lane * 4;
    float4 wl = *(const float4*)(W1l + j);
    float4 wr = *(const float4*)(W1r + j);
    float4 bb = *(const float4*)(b1 + j);
    float v0 = fmaxf(fmaf(mean, wl.x, fmaf(xv, wr.x, bb.x)), 0.0f);
    float v1 = fmaxf(fmaf(mean, wl.y, fmaf(xv, wr.y, bb.y)), 0.0f);
    float v2 = fmaxf(fmaf(mean, wl.z, fmaf(xv, wr.z, bb.z)), 0.0f);
    float v3 = fmaxf(fmaf(mean, wl.w, fmaf(xv, wr.w, bb.w)), 0.0f);
    uint2 o;
    *(__half2*)&o.x = __floats2half2_rn(v0, v1);
    *(__half2*)&o.y = __floats2half2_rn(v2, v3);
    *(uint2*)(g_h1h + (size_t)node * HID + j) = o;
}

// ---------------------------------------------------------------------------
// Weight prep (both layers in one launch): fp16 2-term split.
// chunks 0-3 = Wh (K 0..255), 4-7 = Wl = fp16(W - Wh).
// ---------------------------------------------------------------------------
__global__ void k_prepB(const float* __restrict__ W2l, const float* __restrict__ W2r,
                        const float* __restrict__ W3l, const float* __restrict__ W3r) {
    int t = blockIdx.x * blockDim.x + threadIdx.x;
    if (t >= 2 * 8 * 64 * 64) return;
    int layer = t >> 15;
    int tt = t & 32767;
    const float* Wl = layer ? W3l : W2l;
    const float* Wr = layer ? W3r : W2r;
    int ci = tt >> 12;
    int rem = tt & 4095;
    int k = rem >> 6;
    int np = rem & 63;
    int n = np * 2;
    int kk = (ci & 3) * 64 + k;
    float w0 = (kk < 128) ? Wl[kk * HID + n] : Wr[(kk - 128) * HID + n];
    float w1 = (kk < 128) ? Wl[kk * HID + n + 1] : Wr[(kk - 128) * HID + n + 1];
    __half p0, p1;
    if (ci < 4) {
        p0 = __float2half_rn(w0);
        p1 = __float2half_rn(w1);
    } else {
        __half h0 = __float2half_rn(w0), h1 = __float2half_rn(w1);
        p0 = __float2half_rn(w0 - __half2float(h0));
        p1 = __float2half_rn(w1 - __half2float(h1));
    }
    g_Bp[layer * 34816 + ci * 4352 + k * 68 + np] = pack_h2(p0, p1);
}

// ---------------------------------------------------------------------------
// FUSED gather + SAGE GEMM (fp16 mma, 2-term weight split, K_eff = 512):
//   A-tile row = [mean(node) | hin(node)]; mean gathered IN-KERNEL from CSR.
//   POOL=0: hout = relu(A@W + b) -> fp16  (compiled WITHOUT pool code — R10 regs)
//   POOL=1: relu values accumulated into g_pool (no hout store)
// Template parameter isolates the pool epilogue's register cost to layer 3.
// 64x128 tile / block, 256 threads, occ 3.
// smem: A[64][264 fp16] (33792B) | B dbuf (2x17408B) = 68608B total
// ---------------------------------------------------------------------------
#define AP 528          // A row stride bytes (264 fp16, odd 16B-stride)
#define BP 272          // B row stride bytes (136 fp16)
#define SM_B  33792
#define BCH   17408
#define SMEM_GEMM (33792 + 2 * 17408)

__device__ __forceinline__ void prefB(uint32_t smdst, const uint32_t* src, int tid) {
#pragma unroll
    for (int m = 0; m < 5; m++) {
        int i = tid + m * 256;
        if (i < 1088)
            asm volatile("cp.async.cg.shared.global [%0], [%1], 16;"
                         :: "r"(smdst + i * 16), "l"((const uint4*)src + i) : "memory");
    }
    asm volatile("cp.async.commit_group;" ::: "memory");
}

template <int POOL>
__global__ __launch_bounds__(256, 3)
void k_gemm(const __half* __restrict__ hin, __half* __restrict__ hout,
            const float* __restrict__ bias, const int* __restrict__ batch,
            int layer, int N) {
    extern __shared__ char sm[];
    uint32_t smb = smem_u32(sm);
    int tid = threadIdx.x;
    int lane = tid & 31;
    int wid = tid >> 5;
    int n0 = blockIdx.x * 64;
    const uint32_t* Bpl = g_Bp + layer * 34816;

    // --- Stage hin half-rows via cp.async: 64 rows x 16 chunks = 1024 ---
#pragma unroll
    for (int m = 0; m < 4; m++) {
        int idx = tid + m * 256;
        int r = idx >> 4;
        int c16 = idx & 15;
        int node = n0 + r;
        uint32_t dst = smb + (uint32_t)(r * AP + 256 + c16 * 16);
        if (node < N) {
            const char* src = (const char*)(hin + (size_t)node * HID) + c16 * 16;
            asm volatile("cp.async.cg.shared.global [%0], [%1], 16;"
                         :: "r"(dst), "l"(src) : "memory");
        } else {
            asm volatile("st.shared.v4.b32 [%0], {%1,%1,%1,%1};"
                         :: "r"(dst), "r"(0u) : "memory");
        }
    }
    asm volatile("cp.async.commit_group;" ::: "memory");

    // B chunk 0,1 prefetch (commit groups: hin, c0, c1)
    prefB(smb + SM_B, Bpl, tid);
    prefB(smb + SM_B + BCH, Bpl + 4352, tid);

    // --- In-kernel CSR gather of neighbor means into A cols 0..127 ---
    // Half-warp per node, 4 passes; 2-edge unroll (R10 form).
    {
        int hw = lane >> 4;
        int sl = lane & 15;     // 16B chunk within the 256B mean half-row
#pragma unroll
        for (int pass = 0; pass < 4; pass++) {
            int nl = wid * 8 + pass * 2 + hw;
            int node = n0 + nl;
            float a0 = 0.f, a1 = 0.f, a2 = 0.f, a3 = 0.f;
            float a4 = 0.f, a5 = 0.f, a6 = 0.f, a7 = 0.f;
            float inv = 1.0f;
            if (node < N) {
                int beg = g_rowptr[node], end = g_rowptr[node + 1];
                inv = g_inv[node];
                int i = beg;
                for (; i + 1 < end; i += 2) {
                    int s0 = g_csrc[i], s1 = g_csrc[i + 1];
                    uint4 u0 = __ldg((const uint4*)(hin + (size_t)s0 * HID) + sl);
                    uint4 u1 = __ldg((const uint4*)(hin + (size_t)s1 * HID) + sl);
                    float2 p;
                    p = __half22float2(*(__half2*)&u0.x); a0 += p.x; a1 += p.y;
                    p = __half22float2(*(__half2*)&u0.y); a2 += p.x; a3 += p.y;
                    p = __half22float2(*(__half2*)&u0.z); a4 += p.x; a5 += p.y;
                    p = __half22float2(*(__half2*)&u0.w); a6 += p.x; a7 += p.y;
                    p = __half22float2(*(__half2*)&u1.x); a0 += p.x; a1 += p.y;
                    p = __half22float2(*(__half2*)&u1.y); a2 += p.x; a3 += p.y;
                    p = __half22float2(*(__half2*)&u1.z); a4 += p.x; a5 += p.y;
                    p = __half22float2(*(__half2*)&u1.w); a6 += p.x; a7 += p.y;
                }
                if (i < end) {
                    int s0 = g_csrc[i];
                    uint4 u0 = __ldg((const uint4*)(hin + (size_t)s0 * HID) + sl);
                    float2 p;
                    p = __half22float2(*(__half2*)&u0.x); a0 += p.x; a1 += p.y;
                    p = __half22float2(*(__half2*)&u0.y); a2 += p.x; a3 += p.y;
                    p = __half22float2(*(__half2*)&u0.z); a4 += p.x; a5 += p.y;
                    p = __half22float2(*(__half2*)&u0.w); a6 += p.x; a7 += p.y;
                }
            }
            uint4 o;
            *(__half2*)&o.x = __floats2half2_rn(a0 * inv, a1 * inv);
            *(__half2*)&o.y = __floats2half2_rn(a2 * inv, a3 * inv);
            *(__half2*)&o.z = __floats2half2_rn(a4 * inv, a5 * inv);
            *(__half2*)&o.w = __floats2half2_rn(a6 * inv, a7 * inv);
            uint32_t dst = smb + (uint32_t)(nl * AP + sl * 16);
            asm volatile("st.shared.v4.b32 [%0], {%1,%2,%3,%4};"
                         :: "r"(dst), "r"(o.x), "r"(o.y), "r"(o.z), "r"(o.w)
                         : "memory");
        }
    }

    float acc[2][4][4];
#pragma unroll
    for (int s = 0; s < 2; s++)
#pragma unroll
        for (int nt = 0; nt < 4; nt++)
#pragma unroll
            for (int q = 0; q < 4; q++) acc[s][nt][q] = 0.0f;

    int wr = wid & 1;          // 2 row groups of 32
    int wc = wid >> 1;         // 4 col groups of 32
    int a_r = lane & 15;
    int a_c8 = (lane >> 4) << 3;
    int b_r = lane & 15;

    for (int ci = 0; ci < 8; ci++) {
        if (ci >= 1 && ci < 7)
            prefB(smb + SM_B + ((ci + 1) & 1) * BCH, Bpl + (ci + 1) * 4352, tid);
        if (ci < 7) asm volatile("cp.async.wait_group 1;" ::: "memory");
        else        asm volatile("cp.async.wait_group 0;" ::: "memory");
        __syncthreads();

        int kc = ci & 3;                 // Wh: 0-3, Wl: 4-7 reuse same A cols
        int acol0 = kc * 64;
        uint32_t bbuf = smb + SM_B + (uint32_t)(ci & 1) * BCH;

#pragma unroll
        for (int ks = 0; ks < 4; ks++) {
            int k0 = acol0 + ks * 16;
            uint32_t a0[4], a1[4];
            uint32_t addr0 = smb + (uint32_t)((wr * 32 + a_r) * AP + (k0 + a_c8) * 2);
            ldmatrix_x4(a0, addr0);
            ldmatrix_x4(a1, addr0 + 16 * AP);
            uint32_t bbase = bbuf + (uint32_t)((ks * 16 + b_r) * BP + wc * 64);
#pragma unroll
            for (int nt = 0; nt < 4; nt++) {
                uint32_t b0, b1;
                ldmatrix_x2t(b0, b1, bbase + nt * 16);
                mma_f16(acc[0][nt], a0, b0, b1);
                mma_f16(acc[1][nt], a1, b0, b1);
            }
        }
        __syncthreads();
    }

    int qr = lane >> 2;
    int qc = (lane & 3) * 2;

    if (POOL == 0) {
        // --- Epilogue: bias + relu -> fp16 store (identical to R10) ---
#pragma unroll
        for (int s = 0; s < 2; s++) {
            int mb = n0 + wr * 32 + s * 16;
#pragma unroll
            for (int nt = 0; nt < 4; nt++) {
                int col = wc * 32 + nt * 8 + qc;
                float2 bv = *(const float2*)(bias + col);
                int mlo = mb + qr;
                int mhi = mlo + 8;
                if (mlo < N) {
                    float o0 = fmaxf(acc[s][nt][0] + bv.x, 0.f);
                    float o1 = fmaxf(acc[s][nt][1] + bv.y, 0.f);
                    *(__half2*)(hout + (size_t)mlo * HID + col) = __floats2half2_rn(o0, o1);
                }
                if (mhi < N) {
                    float o0 = fmaxf(acc[s][nt][2] + bv.x, 0.f);
                    float o1 = fmaxf(acc[s][nt][3] + bv.y, 0.f);
                    *(__half2*)(hout + (size_t)mhi * HID + col) = __floats2half2_rn(o0, o1);
                }
            }
        }
    } else {
        // --- Epilogue: bias + relu -> per-block smem pool, then global ---
        float* ps = (float*)(sm + SM_B);   // up to 64 graphs x 128 cols
        int nlast = min(n0 + 63, N - 1);
        int gmin = __ldg(&batch[n0]);
        int gmax = __ldg(&batch[nlast]);
        int ngr = gmax - gmin + 1;
        for (int i = tid; i < ngr * HID; i += 256) ps[i] = 0.0f;
        __syncthreads();
#pragma unroll
        for (int s = 0; s < 2; s++) {
            int mb = n0 + wr * 32 + s * 16;
#pragma unroll
            for (int nt = 0; nt < 4; nt++) {
                int col = wc * 32 + nt * 8 + qc;
                float2 bv = *(const float2*)(bias + col);
                int mlo = mb + qr;
                int mhi = mlo + 8;
                if (mlo < N) {
                    int g = __ldg(&batch[mlo]) - gmin;
                    atomicAdd(&ps[g * HID + col],     fmaxf(acc[s][nt][0] + bv.x, 0.f));
                    atomicAdd(&ps[g * HID + col + 1], fmaxf(acc[s][nt][1] + bv.y, 0.f));
                }
                if (mhi < N) {
                    int g = __ldg(&batch[mhi]) - gmin;
                    atomicAdd(&ps[g * HID + col],     fmaxf(acc[s][nt][2] + bv.x, 0.f));
                    atomicAdd(&ps[g * HID + col + 1], fmaxf(acc[s][nt][3] + bv.y, 0.f));
                }
            }
        }
        __syncthreads();
        for (int i = tid; i < ngr * HID; i += 256)
            atomicAdd(&g_pool[(gmin + i / HID) * HID + (i & 127)], ps[i]);
    }
}

// ---------------------------------------------------------------------------
// Head: logits = (pool/gcnt) @ Wfc + bfc ; log_softmax
// ---------------------------------------------------------------------------
__global__ void k_head(const float* __restrict__ Wfc,
                       const float* __restrict__ bfc,
                       float* __restrict__ out) {
    __shared__ float lg[NG][NC];
    int t = threadIdx.x;
    if (t < NG * NC) {
        int g = t / NC;
        int c = t % NC;
        float ginv = 1.0f / fmaxf(g_gcnt[g], 1.0f);
        float s = __ldg(&bfc[c]);
        for (int k = 0; k < HID; k++)
            s = fmaf(g_pool[g * HID + k] * ginv, __ldg(&Wfc[k * NC + c]), s);
        lg[g][c] = s;
    }
    __syncthreads();
    if (t < NG) {
        float m = -1e30f;
        for (int c = 0; c < NC; c++) m = fmaxf(m, lg[t][c]);
        float se = 0.0f;
        for (int c = 0; c < NC; c++) se += expf(lg[t][c] - m);
        float lse = m + logf(se);
        for (int c = 0; c < NC; c++) out[t * NC + c] = lg[t][c] - lse;
    }
}

// ---------------------------------------------------------------------------
extern "C" void kernel_launch(void* const* d_in, const int* in_sizes, int n_in,
                              void* d_out, int out_size) {
    const float* x   = (const float*)d_in[0];
    const int* ei    = (const int*)d_in[1];
    const int* batch = (const int*)d_in[2];
    const float* W1l = (const float*)d_in[3];
    const float* W1r = (const float*)d_in[4];
    const float* b1  = (const float*)d_in[5];
    const float* W2l = (const float*)d_in[6];
    const float* W2r = (const float*)d_in[7];
    const float* b2  = (const float*)d_in[8];
    const float* W3l = (const float*)d_in[9];
    const float* W3r = (const float*)d_in[10];
    const float* b3  = (const float*)d_in[11];
    const float* Wfc = (const float*)d_in[12];
    const float* bfc = (const float*)d_in[13];
    float* out = (float*)d_out;

    int N = in_sizes[0];
    int E = in_sizes[1] / 2;
    int nb = (N + 255) / 256;

    void *p_deg, *p_gcnt, *p_pool, *p_h1, *p_h2;
    cudaGetSymbolAddress(&p_deg, g_deg);
    cudaGetSymbolAddress(&p_gcnt, g_gcnt);
    cudaGetSymbolAddress(&p_pool, g_pool);
    cudaGetSymbolAddress(&p_h1, g_h1h);
    cudaGetSymbolAddress(&p_h2, g_h2h);

    cudaFuncSetAttribute(k_gemm<0>, cudaFuncAttributeMaxDynamicSharedMemorySize, SMEM_GEMM);
    cudaFuncSetAttribute(k_gemm<1>, cudaFuncAttributeMaxDynamicSharedMemorySize, SMEM_GEMM);

    cudaMemsetAsync(p_deg, 0, (size_t)N * 4);
    cudaMemsetAsync(p_gcnt, 0, NG * 4);
    cudaMemsetAsync(p_pool, 0, NG * HID * 4);

    // CSR build
    k_deg<<<(E + 255) / 256, 256>>>(ei, E);
    k_scan1<<<nb, 256>>>(N);
    k_scan2<<<1, 32>>>(nb, E);
    k_scan3<<<nb, 256>>>(N);
    k_fill<<<(E + 255) / 256, 256>>>(ei, E);

    // Prep + layer 1 (fused CSR scalar agg + transform)
    k_gcnt<<<((N + 31) / 32 + 255) / 256, 256>>>(batch, N);
    k_prepB<<<256, 256>>>(W2l, W2r, W3l, W3r);
    k_layer1f<<<(N + 7) / 8, 256>>>(x, W1l, W1r, b1, N);

    int gemm_blocks = (N + 63) / 64;

    // Layer 2 (fused gather+gemm, no pool code compiled in)
    k_gemm<0><<<gemm_blocks, 256, SMEM_GEMM>>>((const __half*)p_h1, (__half*)p_h2,
                                               b2, batch, 0, N);

    // Layer 3 (fused gather+gemm+pool; no activation store)
    k_gemm<1><<<gemm_blocks, 256, SMEM_GEMM>>>((const __half*)p_h2, (__half*)p_h1,
                                               b3, batch, 1, N);

    // Head
    k_head<<<1, 640>>>(Wfc, bfc, out);
}